// round 4
// baseline (speedup 1.0000x reference)
#include <cuda_runtime.h>
#include <cstdint>
#include <cstddef>

#define BB 8
#define LL 2048
#define HH 8
#define DD 64
#define EE 33
#define UU 40
#define SK 40
#define BHN (BB*HH)
#define ROWS (BHN*LL)

// ---------------- static scratch ----------------
__device__ float2 g_qf [ROWS*EE];
__device__ float2 g_kf [ROWS*EE];
__device__ float2 g_vf [ROWS*EE];
__device__ float2 g_kfT[ROWS*EE];
__device__ float  g_M  [ROWS];
__device__ int    g_top [BHN*UU];
__device__ int    g_slot[ROWS];
__device__ float2 g_upd [BHN*UU*EE];
__device__ float  g_vmt[BHN*DD];
__device__ float2 g_big [(size_t)BHN*UU*LL];

// ---------------- K1: rfft via 32-pt complex DFT + untangle ----------------
__global__ void k_rfft(const float* __restrict__ q,
                       const float* __restrict__ k,
                       const float* __restrict__ v)
{
    __shared__ float2 w32[32], w64[32];
    __shared__ float2 zs[8][32];
    int tid = threadIdx.x;
    if (tid < 32) {
        float s, c;
        sincospif(tid * (1.0f/16.0f), &s, &c);
        w32[tid] = make_float2(c, -s);
        sincospif(tid * (1.0f/32.0f), &s, &c);
        w64[tid] = make_float2(c, -s);
    }
    __syncthreads();
    int warp = tid >> 5, lane = tid & 31;
    int r  = blockIdx.x * 8 + warp;
    int l  = r & (LL - 1);
    int bh = r >> 11;
    int b = bh >> 3, h = bh & 7;
    const float* src = (blockIdx.y == 0) ? q : (blockIdx.y == 1) ? k : v;
    const float2* x2 = (const float2*)(src + (((size_t)b*LL + l)*HH + h) * DD);
    float2 z = x2[lane];
    zs[warp][lane] = z;
    __syncwarp();
    float Zr = 0.f, Zi = 0.f;
    int j = 0;
    #pragma unroll
    for (int n = 0; n < 32; ++n) {
        float2 zn = zs[warp][n];
        float2 w  = w32[j];
        Zr = fmaf(zn.x, w.x, Zr); Zr = fmaf(-zn.y, w.y, Zr);
        Zi = fmaf(zn.x, w.y, Zi); Zi = fmaf( zn.y, w.x, Zi);
        j = (j + lane) & 31;
    }
    int srcl = (32 - lane) & 31;
    float Zmr = __shfl_sync(0xffffffffu, Zr, srcl);
    float Zmi = __shfl_sync(0xffffffffu, Zi, srcl);
    float Zer = 0.5f*(Zr + Zmr), Zei = 0.5f*(Zi - Zmi);
    float Zor = 0.5f*(Zi + Zmi), Zoi = -0.5f*(Zr - Zmr);
    float2 w = w64[lane];
    float Xr = Zer + w.x*Zor - w.y*Zoi;
    float Xi = Zei + w.x*Zoi + w.y*Zor;
    float2* out = (blockIdx.y == 0) ? g_qf : (blockIdx.y == 1) ? g_kf : g_vf;
    out[(size_t)r*EE + lane] = make_float2(Xr, Xi);
    if (lane == 0) out[(size_t)r*EE + 32] = make_float2(Zr - Zi, 0.f);
}

// ---------------- K2: transpose k_fft -> (bh, e, l) ----------------
__global__ void k_transpose()
{
    __shared__ float2 tile[32][EE];
    int bh = blockIdx.y;
    int l0 = blockIdx.x * 32;
    for (int t = threadIdx.x; t < 32*EE; t += 256) {
        int r = t / EE, e = t - r*EE;
        tile[r][e] = g_kf[((size_t)bh*LL + l0 + r)*EE + e];
    }
    __syncthreads();
    for (int t = threadIdx.x; t < EE*32; t += 256) {
        int e = t >> 5, r = t & 31;
        g_kfT[((size_t)bh*EE + e)*LL + l0 + r] = tile[r][e];
    }
}

// ---------------- K2b: time-domain v mean ----------------
__global__ void k_vmt(const float* __restrict__ v)
{
    __shared__ float part[8][64];
    int bh = blockIdx.x, b = bh >> 3, h = bh & 7;
    int tid = threadIdx.x;
    int d = tid & 63, g = tid >> 6;
    const float* base = v + (((size_t)b*LL)*HH + h) * DD + d;
    float acc = 0.f;
    #pragma unroll 8
    for (int i = g; i < LL; i += 8) acc += base[(size_t)i * (HH*DD)];
    part[g][d] = acc;
    __syncthreads();
    if (tid < 64) {
        float s = 0.f;
        #pragma unroll
        for (int g2 = 0; g2 < 8; ++g2) s += part[g2][tid];
        g_vmt[bh*DD + tid] = s * (1.0f/LL);
    }
}

// ---------------- K3: sampled QK -> M, SMEM-resident keys ----------------
// block = (l-group of 256, bh); all 2048 keys for an 8-bin e-chunk live in SMEM.
#define MS_SMEM (2048*8*8 + 2048*4 + 256*8*8 + 256*4 + 256*41*4)
__global__ void __launch_bounds__(256) k_msample(const int* __restrict__ isamp)
{
    extern __shared__ char smem[];
    float2* kbuf = (float2*)smem;                     // [2048*8] swizzled
    float*  kb32 = (float*) (smem + 2048*8*8);        // [2048]
    float2* qch  = (float2*)(smem + 2048*8*8 + 2048*4);              // [256*8] swizzled
    float*  q32  = (float*) (smem + 2048*8*8 + 2048*4 + 256*8*8);    // [256]
    int*    sidx = (int*)   (smem + 2048*8*8 + 2048*4 + 256*8*8 + 256*4); // [256*41] padded

    int tid = threadIdx.x;
    int l0  = blockIdx.x * 256;
    int bh  = blockIdx.y;
    const float2* kT = g_kfT + (size_t)bh*EE*LL;

    // stage sample indices (contiguous, coalesced), padded stride 41
    {
        const int* src = isamp + l0*SK;
        for (int i = tid; i < 256*SK; i += 256) {
            int r = i / SK, s = i - r*SK;
            sidx[r*41 + s] = src[i];
        }
    }
    // stage e=32 bin (real parts only)
    for (int i = tid; i < 2048; i += 256) kb32[i] = kT[(size_t)32*LL + i].x;
    if (tid < 256) q32[tid] = g_qf[((size_t)bh*LL + l0 + tid)*EE + 32].x;

    float accR[SK], accI[SK];
    #pragma unroll
    for (int s = 0; s < SK; ++s) { accR[s] = 0.f; accI[s] = 0.f; }

    #pragma unroll 1
    for (int c = 0; c < 4; ++c) {
        int e0 = c * 8;
        __syncthreads();           // previous chunk fully consumed
        // load kbuf: e-major source -> fully coalesced over l
        for (int i = tid; i < 2048*8; i += 256) {
            int e = i >> 11, r = i & 2047;
            float2 val = kT[(size_t)(e0 + e)*LL + r];
            kbuf[(r << 3) | (e ^ (r & 7))] = val;
        }
        // stage q chunk (64B contiguous per row, 8 threads/row)
        for (int i = tid; i < 256*8; i += 256) {
            int rr = i >> 3, e = i & 7;
            qch[(rr << 3) | (e ^ (rr & 7))] =
                g_qf[((size_t)bh*LL + l0 + rr)*EE + e0 + e];
        }
        __syncthreads();
        float2 qv[8];
        #pragma unroll
        for (int e = 0; e < 8; ++e) qv[e] = qch[(tid << 3) | (e ^ (tid & 7))];
        #pragma unroll
        for (int s = 0; s < SK; ++s) {
            int id = sidx[tid*41 + s];
            int base = id << 3, sw = id & 7;
            #pragma unroll
            for (int e = 0; e < 8; ++e) {
                float2 kv = kbuf[base | (e ^ sw)];
                accR[s] = fmaf(qv[e].x, kv.x, accR[s]);
                accR[s] = fmaf(-qv[e].y, kv.y, accR[s]);
                accI[s] = fmaf(qv[e].x, kv.y, accI[s]);
                accI[s] = fmaf(qv[e].y, kv.x, accI[s]);
            }
        }
    }
    // e = 32 bin: k and q both real -> only Re accumulates
    {
        float qr = q32[tid];
        #pragma unroll
        for (int s = 0; s < SK; ++s) {
            int id = sidx[tid*41 + s];
            accR[s] = fmaf(qr, kb32[id], accR[s]);
        }
    }
    // per-thread reduction over s
    float mr = -3.4e38f, mi = -3.4e38f, sr = 0.f, si = 0.f;
    #pragma unroll
    for (int s = 0; s < SK; ++s) {
        mr = fmaxf(mr, accR[s]); mi = fmaxf(mi, accI[s]);
        sr += accR[s];           si += accI[s];
    }
    g_M[(size_t)bh*LL + l0 + tid] = mr + mi - (sr + si) * (1.0f/LL);
}

// ---------------- K4: top-40 per bh ----------------
__global__ void k_topk()
{
    __shared__ float mv[LL];
    __shared__ float wv[8];
    __shared__ int   wi[8];
    int bh = blockIdx.x, tid = threadIdx.x, lane = tid & 31, warp = tid >> 5;
    for (int i = tid; i < LL; i += 256) {
        mv[i] = g_M[bh*LL + i];
        g_slot[bh*LL + i] = -1;
    }
    __syncthreads();
    for (int u = 0; u < UU; ++u) {
        float best = -3.4e38f; int bi = 1 << 30;
        for (int i = tid; i < LL; i += 256) {
            float x = mv[i];
            if (x > best) { best = x; bi = i; }
        }
        #pragma unroll
        for (int o = 16; o; o >>= 1) {
            float ov = __shfl_xor_sync(0xffffffffu, best, o);
            int   oi = __shfl_xor_sync(0xffffffffu, bi, o);
            if (ov > best || (ov == best && oi < bi)) { best = ov; bi = oi; }
        }
        if (lane == 0) { wv[warp] = best; wi[warp] = bi; }
        __syncthreads();
        if (warp == 0) {
            float b2 = (lane < 8) ? wv[lane] : -3.4e38f;
            int   i2 = (lane < 8) ? wi[lane] : (1 << 30);
            #pragma unroll
            for (int o = 4; o; o >>= 1) {
                float ov = __shfl_xor_sync(0xffffffffu, b2, o);
                int   oi = __shfl_xor_sync(0xffffffffu, i2, o);
                if (ov > b2 || (ov == b2 && oi < i2)) { b2 = ov; i2 = oi; }
            }
            if (lane == 0) {
                g_top[bh*UU + u] = i2;
                g_slot[bh*LL + i2] = u;
                mv[i2] = -3.4e38f;
            }
        }
        __syncthreads();
    }
}

// ---------------- K5: full scores, 20-u register blocked ----------------
__global__ void __launch_bounds__(512) k_scores()
{
    __shared__ float2 shq[20][EE];
    int bh = blockIdx.z;
    int ug = blockIdx.y;
    int jt = blockIdx.x;
    int tid = threadIdx.x;
    for (int t = tid; t < 20*EE; t += 512) {
        int ul = t / EE, e = t - ul*EE;
        int qi = g_top[bh*UU + ug*20 + ul];
        shq[ul][e] = g_qf[((size_t)bh*LL + qi)*EE + e];
    }
    __syncthreads();
    int j = jt*512 + tid;
    float accR[20], accI[20];
    #pragma unroll
    for (int u = 0; u < 20; ++u) { accR[u] = 0.f; accI[u] = 0.f; }
    const float2* kT = g_kfT + (size_t)bh*EE*LL + j;
    for (int e = 0; e < EE; ++e) {
        float2 kv = kT[(size_t)e*LL];
        #pragma unroll
        for (int u = 0; u < 20; ++u) {
            float2 qv = shq[u][e];
            accR[u] = fmaf(qv.x, kv.x, accR[u]); accR[u] = fmaf(-qv.y, kv.y, accR[u]);
            accI[u] = fmaf(qv.x, kv.y, accI[u]); accI[u] = fmaf( qv.y, kv.x, accI[u]);
        }
    }
    const float sc = 0.125f;
    #pragma unroll
    for (int u = 0; u < 20; ++u)
        g_big[((size_t)bh*UU + ug*20 + u)*LL + j] = make_float2(accR[u]*sc, accI[u]*sc);
}

// ---------------- K5b: softmax ----------------
__global__ void k_softmax()
{
    __shared__ float2 sb[LL];
    __shared__ float2 red[256];
    int row = blockIdx.x, tid = threadIdx.x;
    float2* rp = g_big + (size_t)row*LL;
    float mr = -3.4e38f, mi = -3.4e38f;
    for (int i = tid; i < LL; i += 256) {
        float2 v = rp[i]; sb[i] = v;
        mr = fmaxf(mr, v.x); mi = fmaxf(mi, v.y);
    }
    red[tid] = make_float2(mr, mi);
    __syncthreads();
    for (int s = 128; s; s >>= 1) {
        if (tid < s) {
            red[tid].x = fmaxf(red[tid].x, red[tid+s].x);
            red[tid].y = fmaxf(red[tid].y, red[tid+s].y);
        }
        __syncthreads();
    }
    mr = red[0].x; mi = red[0].y;
    __syncthreads();
    float sr = 0.f, si = 0.f;
    for (int i = tid; i < LL; i += 256) {
        float er = __expf(sb[i].x - mr);
        float ei = __expf(sb[i].y - mi);
        sb[i] = make_float2(er, ei);
        sr += er; si += ei;
    }
    red[tid] = make_float2(sr, si);
    __syncthreads();
    for (int s = 128; s; s >>= 1) {
        if (tid < s) { red[tid].x += red[tid+s].x; red[tid].y += red[tid+s].y; }
        __syncthreads();
    }
    float inr = 1.0f / red[0].x, ini = 1.0f / red[0].y;
    for (int i = tid; i < LL; i += 256)
        rp[i] = make_float2(sb[i].x * inr, sb[i].y * ini);
}

// ---------------- K6: upd ----------------
__global__ void __launch_bounds__(256) k_upd()
{
    __shared__ float2 sp[8][256];
    __shared__ float2 accs[8][8][EE];
    int bh = blockIdx.y, ug = blockIdx.x;
    int tid = threadIdx.x, warp = tid >> 5, lane = tid & 31;
    float aR[8], aI[8], aR2[8], aI2[8];
    #pragma unroll
    for (int u = 0; u < 8; ++u) { aR[u]=aI[u]=aR2[u]=aI2[u]=0.f; }
    const float2* vb = g_vf + (size_t)bh*LL*EE;
    for (int c = 0; c < 8; ++c) {
        #pragma unroll
        for (int u = 0; u < 8; ++u)
            sp[u][tid] = g_big[((size_t)bh*UU + ug*8 + u)*LL + c*256 + tid];
        __syncthreads();
        for (int li = warp; li < 256; li += 8) {
            int l = c*256 + li;
            float2 v2 = vb[(size_t)l*EE + lane];
            float2 v32 = make_float2(0.f, 0.f);
            if (lane == 0) v32 = vb[(size_t)l*EE + 32];
            #pragma unroll
            for (int u = 0; u < 8; ++u) {
                float2 p = sp[u][li];
                aR[u]  = fmaf(p.x, v2.x,  aR[u]);
                aI[u]  = fmaf(p.y, v2.y,  aI[u]);
                aR2[u] = fmaf(p.x, v32.x, aR2[u]);
                aI2[u] = fmaf(p.y, v32.y, aI2[u]);
            }
        }
        __syncthreads();
    }
    #pragma unroll
    for (int u = 0; u < 8; ++u) {
        accs[warp][u][lane] = make_float2(aR[u], aI[u]);
        if (lane == 0) accs[warp][u][32] = make_float2(aR2[u], aI2[u]);
    }
    __syncthreads();
    for (int t = tid; t < 8*EE; t += 256) {
        int u = t / EE, e = t - u*EE;
        float sr = 0.f, si = 0.f;
        #pragma unroll
        for (int w = 0; w < 8; ++w) { sr += accs[w][u][e].x; si += accs[w][u][e].y; }
        g_upd[((size_t)bh*UU + ug*8 + u)*EE + e] = make_float2(sr, si);
    }
}

// ---------------- K7: scatter + irfft of selected rows ----------------
__global__ void k_out(float* __restrict__ out)
{
    __shared__ float tc[64], ts[64];
    __shared__ float2 ub[8][EE];
    int tid = threadIdx.x;
    if (tid < 64) {
        float s, c;
        sincospif(tid * (1.0f/32.0f), &s, &c);
        tc[tid] = c; ts[tid] = s;
    }
    __syncthreads();
    int warp = tid >> 5, lane = tid & 31;
    int r = blockIdx.x * 8 + warp;
    int bh = r >> 11;
    int slot = g_slot[r];
    float* op = out + (size_t)r * DD;
    if (slot < 0) {
        op[lane]      = g_vmt[bh*DD + lane];
        op[lane + 32] = g_vmt[bh*DD + lane + 32];
    } else {
        const float2* X = g_upd + ((size_t)bh*UU + slot)*EE;
        ub[warp][lane] = X[lane];
        if (lane == 0) ub[warp][32] = X[32];
        __syncwarp();
        float a0 = ub[warp][0].x;
        float a32 = ub[warp][32].x;
        float sgn = (lane & 1) ? -a32 : a32;
        float acc1 = a0 + sgn, acc2 = a0 + sgn;
        #pragma unroll
        for (int e = 1; e < 32; ++e) {
            float2 Xe = ub[warp][e];
            int j1 = (e * lane) & 63;
            int j2 = (e * (lane + 32)) & 63;
            acc1 += 2.f * (Xe.x*tc[j1] - Xe.y*ts[j1]);
            acc2 += 2.f * (Xe.x*tc[j2] - Xe.y*ts[j2]);
        }
        op[lane]      = acc1 * (1.0f/64.0f);
        op[lane + 32] = acc2 * (1.0f/64.0f);
    }
}

// ---------------- launch ----------------
extern "C" void kernel_launch(void* const* d_in, const int* in_sizes, int n_in,
                              void* d_out, int out_size)
{
    (void)in_sizes; (void)n_in; (void)out_size;
    const float* q = (const float*)d_in[0];
    const float* k = (const float*)d_in[1];
    const float* v = (const float*)d_in[2];
    const int* isamp = (const int*)d_in[4];
    float* out = (float*)d_out;

    cudaFuncSetAttribute(k_msample, cudaFuncAttributeMaxDynamicSharedMemorySize, MS_SMEM);

    k_rfft     <<<dim3(ROWS/8, 3), 256>>>(q, k, v);
    k_transpose<<<dim3(LL/32, BHN), 256>>>();
    k_vmt      <<<BHN, 512>>>(v);
    k_msample  <<<dim3(LL/256, BHN), 256, MS_SMEM>>>(isamp);
    k_topk     <<<BHN, 256>>>();
    k_scores   <<<dim3(4, 2, BHN), 512>>>();
    k_softmax  <<<BHN*UU, 256>>>();
    k_upd      <<<dim3(5, BHN), 256>>>();
    k_out      <<<ROWS/8, 256>>>(out);
}

// round 5
// speedup vs baseline: 1.1509x; 1.1509x over previous
#include <cuda_runtime.h>
#include <cstdint>
#include <cstddef>

#define BB 8
#define LL 2048
#define HH 8
#define DD 64
#define EE 33
#define UU 40
#define SK 40
#define BHN (BB*HH)
#define ROWS (BHN*LL)

// ---------------- static scratch ----------------
__device__ float2 g_qf [ROWS*EE];
__device__ float2 g_kf [ROWS*EE];
__device__ float2 g_vf [ROWS*EE];
__device__ float2 g_kfT[ROWS*EE];
__device__ float  g_M  [ROWS];
__device__ int    g_top [BHN*UU];
__device__ int    g_slot[ROWS];
__device__ float2 g_upd [BHN*UU*EE];
__device__ float  g_vmt[BHN*DD];
__device__ float2 g_big [(size_t)BHN*UU*LL];

__device__ __forceinline__ void cpa8(void* s, const void* g) {
    unsigned sa = (unsigned)__cvta_generic_to_shared(s);
    asm volatile("cp.async.ca.shared.global [%0], [%1], 8;" :: "r"(sa), "l"(g));
}
__device__ __forceinline__ void cp_wait_all() {
    asm volatile("cp.async.wait_all;" ::: "memory");
}

// ---------------- K1: rfft via 5-stage shfl butterfly + untangle ----------------
__global__ void k_rfft(const float* __restrict__ q,
                       const float* __restrict__ k,
                       const float* __restrict__ v)
{
    __shared__ float2 zs[8][32];
    int tid = threadIdx.x;
    int warp = tid >> 5, lane = tid & 31;
    int r  = blockIdx.x * 8 + warp;
    int l  = r & (LL - 1);
    int bh = r >> 11;
    int b = bh >> 3, h = bh & 7;
    const float* src = (blockIdx.y == 0) ? q : (blockIdx.y == 1) ? k : v;
    const float2* x2 = (const float2*)(src + (((size_t)b*LL + l)*HH + h) * DD);
    float2 z = x2[lane];                 // z[n] = x[2n] + i x[2n+1]
    float zr = z.x, zi = z.y;
    // 5-stage radix-2 DIF FFT across lanes; result in bit-reversed lane order
    #pragma unroll
    for (int s = 0; s < 5; ++s) {
        int hm = 16 >> s;
        float orr = __shfl_xor_sync(0xffffffffu, zr, hm);
        float oii = __shfl_xor_sync(0xffffffffu, zi, hm);
        float fr = (float)((lane & (hm - 1)) << s) * (1.0f/16.0f);
        float sn, cs;
        sincospif(fr, &sn, &cs);         // W = cs - i*sn
        float dx = orr - zr, dy = oii - zi;
        float hr = dx*cs + dy*sn;        // (d) * W
        float hi = dy*cs - dx*sn;
        float lr = zr + orr, li = zi + oii;
        bool top = (lane & hm) != 0;
        zr = top ? hr : lr;
        zi = top ? hi : li;
    }
    int bin = __brev((unsigned)lane) >> 27;
    zs[warp][bin] = make_float2(zr, zi);
    __syncwarp();
    float2 m = zs[warp][(32 - bin) & 31];
    // untangle real-input FFT: X = E + W64^bin * O
    float Zer = 0.5f*(zr + m.x), Zei = 0.5f*(zi - m.y);
    float Zor = 0.5f*(zi + m.y), Zoi = -0.5f*(zr - m.x);
    float sn, cs;
    sincospif(bin * (1.0f/32.0f), &sn, &cs);
    float Xr = Zer + cs*Zor + sn*Zoi;
    float Xi = Zei + cs*Zoi - sn*Zor;
    float2* out = (blockIdx.y == 0) ? g_qf : (blockIdx.y == 1) ? g_kf : g_vf;
    out[(size_t)r*EE + bin] = make_float2(Xr, Xi);
    if (bin == 0) out[(size_t)r*EE + 32] = make_float2(zr - zi, 0.f);  // X[32] = Re(Z0)-Im(Z0)
}

// ---------------- K2: transpose k_fft -> (bh, e, l) ----------------
__global__ void k_transpose()
{
    __shared__ float2 tile[32][EE];
    int bh = blockIdx.y;
    int l0 = blockIdx.x * 32;
    for (int t = threadIdx.x; t < 32*EE; t += 256) {
        int r = t / EE, e = t - r*EE;
        tile[r][e] = g_kf[((size_t)bh*LL + l0 + r)*EE + e];
    }
    __syncthreads();
    for (int t = threadIdx.x; t < EE*32; t += 256) {
        int e = t >> 5, r = t & 31;
        g_kfT[((size_t)bh*EE + e)*LL + l0 + r] = tile[r][e];
    }
}

// ---------------- K2b: time-domain v mean ----------------
__global__ void k_vmt(const float* __restrict__ v)
{
    __shared__ float part[8][64];
    int bh = blockIdx.x, b = bh >> 3, h = bh & 7;
    int tid = threadIdx.x;
    int d = tid & 63, g = tid >> 6;
    const float* base = v + (((size_t)b*LL)*HH + h) * DD + d;
    float acc = 0.f;
    #pragma unroll 8
    for (int i = g; i < LL; i += 8) acc += base[(size_t)i * (HH*DD)];
    part[g][d] = acc;
    __syncthreads();
    if (tid < 64) {
        float s = 0.f;
        #pragma unroll
        for (int g2 = 0; g2 < 8; ++g2) s += part[g2][tid];
        g_vmt[bh*DD + tid] = s * (1.0f/LL);
    }
}

// ---------------- K3: sampled QK -> M (cp.async staged, cooperative tail) ----------------
__global__ void __launch_bounds__(256) k_msample(const int* __restrict__ isamp)
{
    __shared__ float2 kbuf[8][SK][17];
    __shared__ float2 qbuf[8][EE];
    __shared__ int    sidx[8][SK];
    __shared__ float2 tails[64];
    int tid = threadIdx.x;
    int warp = tid >> 5, lane = tid & 31;
    int r  = blockIdx.x * 8 + warp;
    int l  = r & (LL - 1);
    int bh = r >> 11;
    // stage sample indices + q row
    const int* iss = isamp + l * SK;
    if (lane < SK) sidx[warp][lane] = iss[lane];
    if (lane + 32 < SK) sidx[warp][lane + 32] = iss[lane + 32];
    qbuf[warp][lane] = g_qf[(size_t)r*EE + lane];
    if (lane == 0) qbuf[warp][32] = g_qf[(size_t)r*EE + 32];
    __syncwarp();
    const float2* kb = g_kf + (size_t)bh*LL*EE;
    // tail assignment: 4 threads per tail dot
    int d  = tid >> 2, p = tid & 3;
    int lw = d >> 3;                   // owner warp/l of this tail dot
    int sT = 32 + (d & 7);             // tail sample index
    float tR = 0.f, tI = 0.f;

    // ---- phase A: bins 0..16 ----
    #pragma unroll 8
    for (int s = 0; s < SK; ++s) {
        int id = sidx[warp][s];
        if (lane < 17) cpa8(&kbuf[warp][s][lane], &kb[(size_t)id*EE + lane]);
    }
    cp_wait_all();
    __syncthreads();
    float dR = 0.f, dI = 0.f;
    #pragma unroll
    for (int e = 0; e < 17; ++e) {
        float2 qv = qbuf[warp][e];
        float2 kv = kbuf[warp][lane][e];
        dR = fmaf(qv.x, kv.x, dR); dR = fmaf(-qv.y, kv.y, dR);
        dI = fmaf(qv.x, kv.y, dI); dI = fmaf( qv.y, kv.x, dI);
    }
    {
        int eBeg = p * 4, eEnd = (p == 3) ? 17 : (p * 4 + 4);
        for (int e = eBeg; e < eEnd; ++e) {
            float2 qv = qbuf[lw][e];
            float2 kv = kbuf[lw][sT][e];
            tR = fmaf(qv.x, kv.x, tR); tR = fmaf(-qv.y, kv.y, tR);
            tI = fmaf(qv.x, kv.y, tI); tI = fmaf( qv.y, kv.x, tI);
        }
    }
    __syncthreads();

    // ---- phase B: bins 17..32 ----
    #pragma unroll 8
    for (int s = 0; s < SK; ++s) {
        int id = sidx[warp][s];
        if (lane < 16) cpa8(&kbuf[warp][s][lane], &kb[(size_t)id*EE + 17 + lane]);
    }
    cp_wait_all();
    __syncthreads();
    #pragma unroll
    for (int e = 0; e < 16; ++e) {
        float2 qv = qbuf[warp][17 + e];
        float2 kv = kbuf[warp][lane][e];
        dR = fmaf(qv.x, kv.x, dR); dR = fmaf(-qv.y, kv.y, dR);
        dI = fmaf(qv.x, kv.y, dI); dI = fmaf( qv.y, kv.x, dI);
    }
    {
        #pragma unroll
        for (int e2 = 0; e2 < 4; ++e2) {
            int e = p * 4 + e2;
            float2 qv = qbuf[lw][17 + e];
            float2 kv = kbuf[lw][sT][e];
            tR = fmaf(qv.x, kv.x, tR); tR = fmaf(-qv.y, kv.y, tR);
            tI = fmaf(qv.x, kv.y, tI); tI = fmaf( qv.y, kv.x, tI);
        }
    }
    // quad-reduce tail partials (p within quad)
    tR += __shfl_xor_sync(0xffffffffu, tR, 1);
    tI += __shfl_xor_sync(0xffffffffu, tI, 1);
    tR += __shfl_xor_sync(0xffffffffu, tR, 2);
    tI += __shfl_xor_sync(0xffffffffu, tI, 2);
    if (p == 0) tails[d] = make_float2(tR, tI);
    __syncthreads();

    // ---- final reduction over 40 samples ----
    float mre = dR, mim = dI, sre = dR, sim = dI;
    if (lane < 8) {
        float2 t = tails[warp*8 + lane];
        mre = fmaxf(mre, t.x); mim = fmaxf(mim, t.y);
        sre += t.x; sim += t.y;
    }
    #pragma unroll
    for (int o = 16; o; o >>= 1) {
        mre = fmaxf(mre, __shfl_xor_sync(0xffffffffu, mre, o));
        mim = fmaxf(mim, __shfl_xor_sync(0xffffffffu, mim, o));
        sre += __shfl_xor_sync(0xffffffffu, sre, o);
        sim += __shfl_xor_sync(0xffffffffu, sim, o);
    }
    if (lane == 0) g_M[r] = mre + mim - (sre + sim) * (1.0f/LL);
}

// ---------------- K4: top-40 per bh ----------------
__global__ void k_topk()
{
    __shared__ float mv[LL];
    __shared__ float wv[8];
    __shared__ int   wi[8];
    int bh = blockIdx.x, tid = threadIdx.x, lane = tid & 31, warp = tid >> 5;
    for (int i = tid; i < LL; i += 256) {
        mv[i] = g_M[bh*LL + i];
        g_slot[bh*LL + i] = -1;
    }
    __syncthreads();
    for (int u = 0; u < UU; ++u) {
        float best = -3.4e38f; int bi = 1 << 30;
        for (int i = tid; i < LL; i += 256) {
            float x = mv[i];
            if (x > best) { best = x; bi = i; }
        }
        #pragma unroll
        for (int o = 16; o; o >>= 1) {
            float ov = __shfl_xor_sync(0xffffffffu, best, o);
            int   oi = __shfl_xor_sync(0xffffffffu, bi, o);
            if (ov > best || (ov == best && oi < bi)) { best = ov; bi = oi; }
        }
        if (lane == 0) { wv[warp] = best; wi[warp] = bi; }
        __syncthreads();
        if (warp == 0) {
            float b2 = (lane < 8) ? wv[lane] : -3.4e38f;
            int   i2 = (lane < 8) ? wi[lane] : (1 << 30);
            #pragma unroll
            for (int o = 4; o; o >>= 1) {
                float ov = __shfl_xor_sync(0xffffffffu, b2, o);
                int   oi = __shfl_xor_sync(0xffffffffu, i2, o);
                if (ov > b2 || (ov == b2 && oi < i2)) { b2 = ov; i2 = oi; }
            }
            if (lane == 0) {
                g_top[bh*UU + u] = i2;
                g_slot[bh*LL + i2] = u;
                mv[i2] = -3.4e38f;
            }
        }
        __syncthreads();
    }
}

// ---------------- K5: full scores, 20-u register blocked ----------------
__global__ void __launch_bounds__(512) k_scores()
{
    __shared__ float2 shq[20][EE];
    int bh = blockIdx.z;
    int ug = blockIdx.y;
    int jt = blockIdx.x;
    int tid = threadIdx.x;
    for (int t = tid; t < 20*EE; t += 512) {
        int ul = t / EE, e = t - ul*EE;
        int qi = g_top[bh*UU + ug*20 + ul];
        shq[ul][e] = g_qf[((size_t)bh*LL + qi)*EE + e];
    }
    __syncthreads();
    int j = jt*512 + tid;
    float accR[20], accI[20];
    #pragma unroll
    for (int u = 0; u < 20; ++u) { accR[u] = 0.f; accI[u] = 0.f; }
    const float2* kT = g_kfT + (size_t)bh*EE*LL + j;
    for (int e = 0; e < EE; ++e) {
        float2 kv = kT[(size_t)e*LL];
        #pragma unroll
        for (int u = 0; u < 20; ++u) {
            float2 qv = shq[u][e];
            accR[u] = fmaf(qv.x, kv.x, accR[u]); accR[u] = fmaf(-qv.y, kv.y, accR[u]);
            accI[u] = fmaf(qv.x, kv.y, accI[u]); accI[u] = fmaf( qv.y, kv.x, accI[u]);
        }
    }
    const float sc = 0.125f;
    #pragma unroll
    for (int u = 0; u < 20; ++u)
        g_big[((size_t)bh*UU + ug*20 + u)*LL + j] = make_float2(accR[u]*sc, accI[u]*sc);
}

// ---------------- K5b: softmax ----------------
__global__ void k_softmax()
{
    __shared__ float2 sb[LL];
    __shared__ float2 red[256];
    int row = blockIdx.x, tid = threadIdx.x;
    float2* rp = g_big + (size_t)row*LL;
    float mr = -3.4e38f, mi = -3.4e38f;
    for (int i = tid; i < LL; i += 256) {
        float2 v = rp[i]; sb[i] = v;
        mr = fmaxf(mr, v.x); mi = fmaxf(mi, v.y);
    }
    red[tid] = make_float2(mr, mi);
    __syncthreads();
    for (int s = 128; s; s >>= 1) {
        if (tid < s) {
            red[tid].x = fmaxf(red[tid].x, red[tid+s].x);
            red[tid].y = fmaxf(red[tid].y, red[tid+s].y);
        }
        __syncthreads();
    }
    mr = red[0].x; mi = red[0].y;
    __syncthreads();
    float sr = 0.f, si = 0.f;
    for (int i = tid; i < LL; i += 256) {
        float er = __expf(sb[i].x - mr);
        float ei = __expf(sb[i].y - mi);
        sb[i] = make_float2(er, ei);
        sr += er; si += ei;
    }
    red[tid] = make_float2(sr, si);
    __syncthreads();
    for (int s = 128; s; s >>= 1) {
        if (tid < s) { red[tid].x += red[tid+s].x; red[tid].y += red[tid+s].y; }
        __syncthreads();
    }
    float inr = 1.0f / red[0].x, ini = 1.0f / red[0].y;
    for (int i = tid; i < LL; i += 256)
        rp[i] = make_float2(sb[i].x * inr, sb[i].y * ini);
}

// ---------------- K6: upd ----------------
__global__ void __launch_bounds__(256) k_upd()
{
    __shared__ float2 sp[8][256];
    __shared__ float2 accs[8][8][EE];
    int bh = blockIdx.y, ug = blockIdx.x;
    int tid = threadIdx.x, warp = tid >> 5, lane = tid & 31;
    float aR[8], aI[8], aR2[8], aI2[8];
    #pragma unroll
    for (int u = 0; u < 8; ++u) { aR[u]=aI[u]=aR2[u]=aI2[u]=0.f; }
    const float2* vb = g_vf + (size_t)bh*LL*EE;
    for (int c = 0; c < 8; ++c) {
        #pragma unroll
        for (int u = 0; u < 8; ++u)
            sp[u][tid] = g_big[((size_t)bh*UU + ug*8 + u)*LL + c*256 + tid];
        __syncthreads();
        for (int li = warp; li < 256; li += 8) {
            int l = c*256 + li;
            float2 v2 = vb[(size_t)l*EE + lane];
            float2 v32 = make_float2(0.f, 0.f);
            if (lane == 0) v32 = vb[(size_t)l*EE + 32];
            #pragma unroll
            for (int u = 0; u < 8; ++u) {
                float2 pp = sp[u][li];
                aR[u]  = fmaf(pp.x, v2.x,  aR[u]);
                aI[u]  = fmaf(pp.y, v2.y,  aI[u]);
                aR2[u] = fmaf(pp.x, v32.x, aR2[u]);
                aI2[u] = fmaf(pp.y, v32.y, aI2[u]);
            }
        }
        __syncthreads();
    }
    #pragma unroll
    for (int u = 0; u < 8; ++u) {
        accs[warp][u][lane] = make_float2(aR[u], aI[u]);
        if (lane == 0) accs[warp][u][32] = make_float2(aR2[u], aI2[u]);
    }
    __syncthreads();
    for (int t = tid; t < 8*EE; t += 256) {
        int u = t / EE, e = t - u*EE;
        float sr = 0.f, si = 0.f;
        #pragma unroll
        for (int w = 0; w < 8; ++w) { sr += accs[w][u][e].x; si += accs[w][u][e].y; }
        g_upd[((size_t)bh*UU + ug*8 + u)*EE + e] = make_float2(sr, si);
    }
}

// ---------------- K7: scatter + irfft of selected rows ----------------
__global__ void k_out(float* __restrict__ out)
{
    __shared__ float tc[64], ts[64];
    __shared__ float2 ub[8][EE];
    int tid = threadIdx.x;
    if (tid < 64) {
        float s, c;
        sincospif(tid * (1.0f/32.0f), &s, &c);
        tc[tid] = c; ts[tid] = s;
    }
    __syncthreads();
    int warp = tid >> 5, lane = tid & 31;
    int r = blockIdx.x * 8 + warp;
    int bh = r >> 11;
    int slot = g_slot[r];
    float* op = out + (size_t)r * DD;
    if (slot < 0) {
        op[lane]      = g_vmt[bh*DD + lane];
        op[lane + 32] = g_vmt[bh*DD + lane + 32];
    } else {
        const float2* X = g_upd + ((size_t)bh*UU + slot)*EE;
        ub[warp][lane] = X[lane];
        if (lane == 0) ub[warp][32] = X[32];
        __syncwarp();
        float a0 = ub[warp][0].x;
        float a32 = ub[warp][32].x;
        float sgn = (lane & 1) ? -a32 : a32;
        float acc1 = a0 + sgn, acc2 = a0 + sgn;
        #pragma unroll
        for (int e = 1; e < 32; ++e) {
            float2 Xe = ub[warp][e];
            int j1 = (e * lane) & 63;
            int j2 = (e * (lane + 32)) & 63;
            acc1 += 2.f * (Xe.x*tc[j1] - Xe.y*ts[j1]);
            acc2 += 2.f * (Xe.x*tc[j2] - Xe.y*ts[j2]);
        }
        op[lane]      = acc1 * (1.0f/64.0f);
        op[lane + 32] = acc2 * (1.0f/64.0f);
    }
}

// ---------------- launch ----------------
extern "C" void kernel_launch(void* const* d_in, const int* in_sizes, int n_in,
                              void* d_out, int out_size)
{
    (void)in_sizes; (void)n_in; (void)out_size;
    const float* q = (const float*)d_in[0];
    const float* k = (const float*)d_in[1];
    const float* v = (const float*)d_in[2];
    const int* isamp = (const int*)d_in[4];
    float* out = (float*)d_out;

    k_rfft     <<<dim3(ROWS/8, 3), 256>>>(q, k, v);
    k_transpose<<<dim3(LL/32, BHN), 256>>>();
    k_vmt      <<<BHN, 512>>>(v);
    k_msample  <<<ROWS/8, 256>>>(isamp);
    k_topk     <<<BHN, 256>>>();
    k_scores   <<<dim3(4, 2, BHN), 512>>>();
    k_softmax  <<<BHN*UU, 256>>>();
    k_upd      <<<dim3(5, BHN), 256>>>();
    k_out      <<<ROWS/8, 256>>>(out);
}

// round 6
// speedup vs baseline: 1.5606x; 1.3560x over previous
#include <cuda_runtime.h>
#include <cstdint>
#include <cstddef>

#define BB 8
#define LL 2048
#define HH 8
#define DD 64
#define EE 33
#define UU 40
#define SK 40
#define BHN (BB*HH)
#define ROWS (BHN*LL)

// ---------------- static scratch ----------------
__device__ float2 g_qf [ROWS*EE];
__device__ float2 g_kf [ROWS*EE];
__device__ float2 g_vf [ROWS*EE];
__device__ float2 g_kfT[ROWS*EE];
__device__ float4 g_kfC[(size_t)BHN*8*4096];   // [bh][chunk(8)][id*2+half] 4-bin chunks
__device__ float  g_k32[BHN*LL];
__device__ float  g_M  [ROWS];
__device__ int    g_top [BHN*UU];
__device__ int    g_slot[ROWS];
__device__ float2 g_upd [BHN*UU*EE];
__device__ float  g_vmt[BHN*DD];
__device__ float2 g_big [(size_t)BHN*UU*LL];

__device__ __forceinline__ void cpa16(void* s, const void* g) {
    unsigned sa = (unsigned)__cvta_generic_to_shared(s);
    asm volatile("cp.async.cg.shared.global [%0], [%1], 16;" :: "r"(sa), "l"(g));
}
__device__ __forceinline__ void cp_commit() {
    asm volatile("cp.async.commit_group;" ::: "memory");
}
__device__ __forceinline__ void cp_wait1() {
    asm volatile("cp.async.wait_group 1;" ::: "memory");
}
__device__ __forceinline__ void cp_wait0() {
    asm volatile("cp.async.wait_group 0;" ::: "memory");
}

// ---------------- K1: rfft via 5-stage shfl butterfly + untangle ----------------
__global__ void k_rfft(const float* __restrict__ q,
                       const float* __restrict__ k,
                       const float* __restrict__ v)
{
    __shared__ float2 zs[8][32];
    int tid = threadIdx.x;
    int warp = tid >> 5, lane = tid & 31;
    int r  = blockIdx.x * 8 + warp;
    int l  = r & (LL - 1);
    int bh = r >> 11;
    int b = bh >> 3, h = bh & 7;
    const float* src = (blockIdx.y == 0) ? q : (blockIdx.y == 1) ? k : v;
    const float2* x2 = (const float2*)(src + (((size_t)b*LL + l)*HH + h) * DD);
    float2 z = x2[lane];
    float zr = z.x, zi = z.y;
    #pragma unroll
    for (int s = 0; s < 5; ++s) {
        int hm = 16 >> s;
        float orr = __shfl_xor_sync(0xffffffffu, zr, hm);
        float oii = __shfl_xor_sync(0xffffffffu, zi, hm);
        float fr = (float)((lane & (hm - 1)) << s) * (1.0f/16.0f);
        float sn, cs;
        sincospif(fr, &sn, &cs);
        float dx = orr - zr, dy = oii - zi;
        float hr = dx*cs + dy*sn;
        float hi = dy*cs - dx*sn;
        float lr = zr + orr, li = zi + oii;
        bool top = (lane & hm) != 0;
        zr = top ? hr : lr;
        zi = top ? hi : li;
    }
    int bin = __brev((unsigned)lane) >> 27;
    zs[warp][bin] = make_float2(zr, zi);
    __syncwarp();
    float2 m = zs[warp][(32 - bin) & 31];
    float Zer = 0.5f*(zr + m.x), Zei = 0.5f*(zi - m.y);
    float Zor = 0.5f*(zi + m.y), Zoi = -0.5f*(zr - m.x);
    float sn, cs;
    sincospif(bin * (1.0f/32.0f), &sn, &cs);
    float Xr = Zer + cs*Zor + sn*Zoi;
    float Xi = Zei + cs*Zoi - sn*Zor;
    float2* out = (blockIdx.y == 0) ? g_qf : (blockIdx.y == 1) ? g_kf : g_vf;
    out[(size_t)r*EE + bin] = make_float2(Xr, Xi);
    if (bin == 0) out[(size_t)r*EE + 32] = make_float2(zr - zi, 0.f);
}

// ---------------- K2: transpose k_fft -> e-major + chunked row-major ----------------
__global__ void k_transpose()
{
    __shared__ float2 tile[32][EE];
    int bh = blockIdx.y;
    int l0 = blockIdx.x * 32;
    for (int t = threadIdx.x; t < 32*EE; t += 256) {
        int r = t / EE, e = t - r*EE;
        tile[r][e] = g_kf[((size_t)bh*LL + l0 + r)*EE + e];
    }
    __syncthreads();
    for (int t = threadIdx.x; t < EE*32; t += 256) {
        int e = t >> 5, r = t & 31;
        g_kfT[((size_t)bh*EE + e)*LL + l0 + r] = tile[r][e];
    }
    // chunked layout: 8 chunks x 4 bins -> float4 halves
    for (int t = threadIdx.x; t < 512; t += 256) {
        int half = t >> 8;
        int c    = (t >> 5) & 7;
        int r    = t & 31;
        float2 a = tile[r][c*4 + half*2];
        float2 b = tile[r][c*4 + half*2 + 1];
        g_kfC[(((size_t)(bh*8 + c)) << 12) + (size_t)(l0 + r)*2 + half] =
            make_float4(a.x, a.y, b.x, b.y);
    }
    if (threadIdx.x < 32)
        g_k32[bh*LL + l0 + threadIdx.x] = tile[threadIdx.x][32].x;
}

// ---------------- K2b: time-domain v mean ----------------
__global__ void k_vmt(const float* __restrict__ v)
{
    __shared__ float part[8][64];
    int bh = blockIdx.x, b = bh >> 3, h = bh & 7;
    int tid = threadIdx.x;
    int d = tid & 63, g = tid >> 6;
    const float* base = v + (((size_t)b*LL)*HH + h) * DD + d;
    float acc = 0.f;
    #pragma unroll 8
    for (int i = g; i < LL; i += 8) acc += base[(size_t)i * (HH*DD)];
    part[g][d] = acc;
    __syncthreads();
    if (tid < 64) {
        float s = 0.f;
        #pragma unroll
        for (int g2 = 0; g2 < 8; ++g2) s += part[g2][tid];
        g_vmt[bh*DD + tid] = s * (1.0f/LL);
    }
}

// ---------------- K3: sampled QK -> M, smem-resident keys, double-buffered ----------------
// block = (l-group of 256, bh), 1024 threads; thread = (l, sample-decile of 10)
#define MS_SMEM (131072 + 8192 + 16384)
__global__ void __launch_bounds__(1024, 1) k_msample(const int* __restrict__ isamp)
{
    extern __shared__ char sm[];
    float4* kbuf = (float4*)sm;                        // [2][4096] swizzled, 128KB
    float*  sk32 = (float*)(sm + 131072);              // [2048]
    float4* pt   = (float4*)(sm + 131072 + 8192);      // [4][256]

    int tid = threadIdx.x;
    int l0  = blockIdx.x * 256;
    int bh  = blockIdx.y;
    int sg  = tid & 3;
    int lq  = tid >> 2;
    int l   = l0 + lq;

    // stage e=32 keys
    sk32[tid]        = g_k32[bh*LL + tid];
    sk32[tid + 1024] = g_k32[bh*LL + tid + 1024];

    // this thread's 10 sample indices
    const int* ip = isamp + l*SK + sg*10;
    int ids[10];
    #pragma unroll
    for (int i = 0; i < 10; ++i) ids[i] = ip[i];

    const float4* kc = g_kfC + (((size_t)(bh*8)) << 12);
    // prologue: chunk 0 -> buf 0
    #pragma unroll
    for (int it = 0; it < 4; ++it) {
        int lin = it*1024 + tid;
        int sw  = lin ^ ((lin >> 3) & 7);
        cpa16(&kbuf[sw], &kc[lin]);
    }
    cp_commit();

    float accR[10], accI[10];
    #pragma unroll
    for (int s = 0; s < 10; ++s) { accR[s] = 0.f; accI[s] = 0.f; }
    const float2* qrow = g_qf + (size_t)(bh*LL + l)*EE;

    #pragma unroll 1
    for (int c = 0; c < 8; ++c) {
        int cur = (c & 1) << 12;
        if (c < 7) {
            const float4* src = kc + ((size_t)(c+1) << 12);
            int nb = ((c+1) & 1) << 12;
            #pragma unroll
            for (int it = 0; it < 4; ++it) {
                int lin = it*1024 + tid;
                int sw  = lin ^ ((lin >> 3) & 7);
                cpa16(&kbuf[nb + sw], &src[lin]);
            }
            cp_commit();
            cp_wait1();
        } else {
            cp_wait0();
        }
        __syncthreads();
        float2 q0 = qrow[4*c], q1 = qrow[4*c+1], q2 = qrow[4*c+2], q3 = qrow[4*c+3];
        #pragma unroll
        for (int s = 0; s < 10; ++s) {
            int id = ids[s];
            int p = id << 1, x = (id >> 2) & 7;
            float4 h0 = kbuf[cur + (p ^ x)];
            float4 h1 = kbuf[cur + ((p + 1) ^ x)];
            accR[s] = fmaf(q0.x, h0.x, accR[s]); accR[s] = fmaf(-q0.y, h0.y, accR[s]);
            accI[s] = fmaf(q0.x, h0.y, accI[s]); accI[s] = fmaf( q0.y, h0.x, accI[s]);
            accR[s] = fmaf(q1.x, h0.z, accR[s]); accR[s] = fmaf(-q1.y, h0.w, accR[s]);
            accI[s] = fmaf(q1.x, h0.w, accI[s]); accI[s] = fmaf( q1.y, h0.z, accI[s]);
            accR[s] = fmaf(q2.x, h1.x, accR[s]); accR[s] = fmaf(-q2.y, h1.y, accR[s]);
            accI[s] = fmaf(q2.x, h1.y, accI[s]); accI[s] = fmaf( q2.y, h1.x, accI[s]);
            accR[s] = fmaf(q3.x, h1.z, accR[s]); accR[s] = fmaf(-q3.y, h1.w, accR[s]);
            accI[s] = fmaf(q3.x, h1.w, accI[s]); accI[s] = fmaf( q3.y, h1.z, accI[s]);
        }
        __syncthreads();
    }
    // e = 32 bin (both real)
    {
        float q32 = qrow[32].x;
        #pragma unroll
        for (int s = 0; s < 10; ++s)
            accR[s] = fmaf(q32, sk32[ids[s]], accR[s]);
    }
    // per-thread reduce over 10 samples
    float mr = -3.4e38f, mi = -3.4e38f, sr = 0.f, si = 0.f;
    #pragma unroll
    for (int s = 0; s < 10; ++s) {
        mr = fmaxf(mr, accR[s]); mi = fmaxf(mi, accI[s]);
        sr += accR[s];           si += accI[s];
    }
    pt[sg*256 + lq] = make_float4(mr, mi, sr, si);
    __syncthreads();
    if (tid < 256) {
        float4 a = pt[tid], b = pt[256 + tid], c2 = pt[512 + tid], d = pt[768 + tid];
        float MR = fmaxf(fmaxf(a.x, b.x), fmaxf(c2.x, d.x));
        float MI = fmaxf(fmaxf(a.y, b.y), fmaxf(c2.y, d.y));
        float SR = a.z + b.z + c2.z + d.z;
        float SI = a.w + b.w + c2.w + d.w;
        g_M[(size_t)bh*LL + l0 + tid] = MR + MI - (SR + SI) * (1.0f/LL);
    }
}

// ---------------- K4: top-40 per bh ----------------
__global__ void k_topk()
{
    __shared__ float mv[LL];
    __shared__ float wv[8];
    __shared__ int   wi[8];
    int bh = blockIdx.x, tid = threadIdx.x, lane = tid & 31, warp = tid >> 5;
    for (int i = tid; i < LL; i += 256) {
        mv[i] = g_M[bh*LL + i];
        g_slot[bh*LL + i] = -1;
    }
    __syncthreads();
    for (int u = 0; u < UU; ++u) {
        float best = -3.4e38f; int bi = 1 << 30;
        for (int i = tid; i < LL; i += 256) {
            float x = mv[i];
            if (x > best) { best = x; bi = i; }
        }
        #pragma unroll
        for (int o = 16; o; o >>= 1) {
            float ov = __shfl_xor_sync(0xffffffffu, best, o);
            int   oi = __shfl_xor_sync(0xffffffffu, bi, o);
            if (ov > best || (ov == best && oi < bi)) { best = ov; bi = oi; }
        }
        if (lane == 0) { wv[warp] = best; wi[warp] = bi; }
        __syncthreads();
        if (warp == 0) {
            float b2 = (lane < 8) ? wv[lane] : -3.4e38f;
            int   i2 = (lane < 8) ? wi[lane] : (1 << 30);
            #pragma unroll
            for (int o = 4; o; o >>= 1) {
                float ov = __shfl_xor_sync(0xffffffffu, b2, o);
                int   oi = __shfl_xor_sync(0xffffffffu, i2, o);
                if (ov > b2 || (ov == b2 && oi < i2)) { b2 = ov; i2 = oi; }
            }
            if (lane == 0) {
                g_top[bh*UU + u] = i2;
                g_slot[bh*LL + i2] = u;
                mv[i2] = -3.4e38f;
            }
        }
        __syncthreads();
    }
}

// ---------------- K5: full scores, 20-u register blocked ----------------
__global__ void __launch_bounds__(512) k_scores()
{
    __shared__ float2 shq[20][EE];
    int bh = blockIdx.z;
    int ug = blockIdx.y;
    int jt = blockIdx.x;
    int tid = threadIdx.x;
    for (int t = tid; t < 20*EE; t += 512) {
        int ul = t / EE, e = t - ul*EE;
        int qi = g_top[bh*UU + ug*20 + ul];
        shq[ul][e] = g_qf[((size_t)bh*LL + qi)*EE + e];
    }
    __syncthreads();
    int j = jt*512 + tid;
    float accR[20], accI[20];
    #pragma unroll
    for (int u = 0; u < 20; ++u) { accR[u] = 0.f; accI[u] = 0.f; }
    const float2* kT = g_kfT + (size_t)bh*EE*LL + j;
    for (int e = 0; e < EE; ++e) {
        float2 kv = kT[(size_t)e*LL];
        #pragma unroll
        for (int u = 0; u < 20; ++u) {
            float2 qv = shq[u][e];
            accR[u] = fmaf(qv.x, kv.x, accR[u]); accR[u] = fmaf(-qv.y, kv.y, accR[u]);
            accI[u] = fmaf(qv.x, kv.y, accI[u]); accI[u] = fmaf( qv.y, kv.x, accI[u]);
        }
    }
    const float sc = 0.125f;
    #pragma unroll
    for (int u = 0; u < 20; ++u)
        g_big[((size_t)bh*UU + ug*20 + u)*LL + j] = make_float2(accR[u]*sc, accI[u]*sc);
}

// ---------------- K5b: softmax ----------------
__global__ void k_softmax()
{
    __shared__ float2 sb[LL];
    __shared__ float2 red[256];
    int row = blockIdx.x, tid = threadIdx.x;
    float2* rp = g_big + (size_t)row*LL;
    float mr = -3.4e38f, mi = -3.4e38f;
    for (int i = tid; i < LL; i += 256) {
        float2 v = rp[i]; sb[i] = v;
        mr = fmaxf(mr, v.x); mi = fmaxf(mi, v.y);
    }
    red[tid] = make_float2(mr, mi);
    __syncthreads();
    for (int s = 128; s; s >>= 1) {
        if (tid < s) {
            red[tid].x = fmaxf(red[tid].x, red[tid+s].x);
            red[tid].y = fmaxf(red[tid].y, red[tid+s].y);
        }
        __syncthreads();
    }
    mr = red[0].x; mi = red[0].y;
    __syncthreads();
    float sr = 0.f, si = 0.f;
    for (int i = tid; i < LL; i += 256) {
        float er = __expf(sb[i].x - mr);
        float ei = __expf(sb[i].y - mi);
        sb[i] = make_float2(er, ei);
        sr += er; si += ei;
    }
    red[tid] = make_float2(sr, si);
    __syncthreads();
    for (int s = 128; s; s >>= 1) {
        if (tid < s) { red[tid].x += red[tid+s].x; red[tid].y += red[tid+s].y; }
        __syncthreads();
    }
    float inr = 1.0f / red[0].x, ini = 1.0f / red[0].y;
    for (int i = tid; i < LL; i += 256)
        rp[i] = make_float2(sb[i].x * inr, sb[i].y * ini);
}

// ---------------- K6: upd ----------------
__global__ void __launch_bounds__(256) k_upd()
{
    __shared__ float2 sp[8][256];
    __shared__ float2 accs[8][8][EE];
    int bh = blockIdx.y, ug = blockIdx.x;
    int tid = threadIdx.x, warp = tid >> 5, lane = tid & 31;
    float aR[8], aI[8], aR2[8], aI2[8];
    #pragma unroll
    for (int u = 0; u < 8; ++u) { aR[u]=aI[u]=aR2[u]=aI2[u]=0.f; }
    const float2* vb = g_vf + (size_t)bh*LL*EE;
    for (int c = 0; c < 8; ++c) {
        #pragma unroll
        for (int u = 0; u < 8; ++u)
            sp[u][tid] = g_big[((size_t)bh*UU + ug*8 + u)*LL + c*256 + tid];
        __syncthreads();
        for (int li = warp; li < 256; li += 8) {
            int l = c*256 + li;
            float2 v2 = vb[(size_t)l*EE + lane];
            float2 v32 = make_float2(0.f, 0.f);
            if (lane == 0) v32 = vb[(size_t)l*EE + 32];
            #pragma unroll
            for (int u = 0; u < 8; ++u) {
                float2 pp = sp[u][li];
                aR[u]  = fmaf(pp.x, v2.x,  aR[u]);
                aI[u]  = fmaf(pp.y, v2.y,  aI[u]);
                aR2[u] = fmaf(pp.x, v32.x, aR2[u]);
                aI2[u] = fmaf(pp.y, v32.y, aI2[u]);
            }
        }
        __syncthreads();
    }
    #pragma unroll
    for (int u = 0; u < 8; ++u) {
        accs[warp][u][lane] = make_float2(aR[u], aI[u]);
        if (lane == 0) accs[warp][u][32] = make_float2(aR2[u], aI2[u]);
    }
    __syncthreads();
    for (int t = tid; t < 8*EE; t += 256) {
        int u = t / EE, e = t - u*EE;
        float sr = 0.f, si = 0.f;
        #pragma unroll
        for (int w = 0; w < 8; ++w) { sr += accs[w][u][e].x; si += accs[w][u][e].y; }
        g_upd[((size_t)bh*UU + ug*8 + u)*EE + e] = make_float2(sr, si);
    }
}

// ---------------- K7: scatter + irfft of selected rows ----------------
__global__ void k_out(float* __restrict__ out)
{
    __shared__ float tc[64], ts[64];
    __shared__ float2 ub[8][EE];
    int tid = threadIdx.x;
    if (tid < 64) {
        float s, c;
        sincospif(tid * (1.0f/32.0f), &s, &c);
        tc[tid] = c; ts[tid] = s;
    }
    __syncthreads();
    int warp = tid >> 5, lane = tid & 31;
    int r = blockIdx.x * 8 + warp;
    int bh = r >> 11;
    int slot = g_slot[r];
    float* op = out + (size_t)r * DD;
    if (slot < 0) {
        op[lane]      = g_vmt[bh*DD + lane];
        op[lane + 32] = g_vmt[bh*DD + lane + 32];
    } else {
        const float2* X = g_upd + ((size_t)bh*UU + slot)*EE;
        ub[warp][lane] = X[lane];
        if (lane == 0) ub[warp][32] = X[32];
        __syncwarp();
        float a0 = ub[warp][0].x;
        float a32 = ub[warp][32].x;
        float sgn = (lane & 1) ? -a32 : a32;
        float acc1 = a0 + sgn, acc2 = a0 + sgn;
        #pragma unroll
        for (int e = 1; e < 32; ++e) {
            float2 Xe = ub[warp][e];
            int j1 = (e * lane) & 63;
            int j2 = (e * (lane + 32)) & 63;
            acc1 += 2.f * (Xe.x*tc[j1] - Xe.y*ts[j1]);
            acc2 += 2.f * (Xe.x*tc[j2] - Xe.y*ts[j2]);
        }
        op[lane]      = acc1 * (1.0f/64.0f);
        op[lane + 32] = acc2 * (1.0f/64.0f);
    }
}

// ---------------- launch ----------------
extern "C" void kernel_launch(void* const* d_in, const int* in_sizes, int n_in,
                              void* d_out, int out_size)
{
    (void)in_sizes; (void)n_in; (void)out_size;
    const float* q = (const float*)d_in[0];
    const float* k = (const float*)d_in[1];
    const float* v = (const float*)d_in[2];
    const int* isamp = (const int*)d_in[4];
    float* out = (float*)d_out;

    cudaFuncSetAttribute(k_msample, cudaFuncAttributeMaxDynamicSharedMemorySize, MS_SMEM);

    k_rfft     <<<dim3(ROWS/8, 3), 256>>>(q, k, v);
    k_transpose<<<dim3(LL/32, BHN), 256>>>();
    k_vmt      <<<BHN, 512>>>(v);
    k_msample  <<<dim3(LL/256, BHN), 1024, MS_SMEM>>>(isamp);
    k_topk     <<<BHN, 256>>>();
    k_scores   <<<dim3(4, 2, BHN), 512>>>();
    k_softmax  <<<BHN*UU, 256>>>();
    k_upd      <<<dim3(5, BHN), 256>>>();
    k_out      <<<ROWS/8, 256>>>(out);
}

// round 7
// speedup vs baseline: 1.5952x; 1.0221x over previous
#include <cuda_runtime.h>
#include <cstdint>
#include <cstddef>

#define BB 8
#define LL 2048
#define HH 8
#define DD 64
#define EE 33
#define UU 40
#define SK 40
#define BHN (BB*HH)
#define ROWS (BHN*LL)

// ---------------- static scratch ----------------
__device__ float2 g_qf [ROWS*EE];
__device__ float2 g_kf [ROWS*EE];
__device__ float2 g_vf [ROWS*EE];
__device__ float2 g_kfT[ROWS*EE];
__device__ float4 g_kfC[(size_t)BHN*8*4096];
__device__ float  g_k32[BHN*LL];
__device__ float  g_M  [ROWS];
__device__ int    g_top [BHN*UU];
__device__ int    g_slot[ROWS];
__device__ float2 g_upd [BHN*UU*EE];
__device__ float  g_vmt[BHN*DD];
__device__ float2 g_big [(size_t)BHN*UU*LL];

__device__ __forceinline__ void cpa16(void* s, const void* g) {
    unsigned sa = (unsigned)__cvta_generic_to_shared(s);
    asm volatile("cp.async.cg.shared.global [%0], [%1], 16;" :: "r"(sa), "l"(g));
}
__device__ __forceinline__ void cp_commit() {
    asm volatile("cp.async.commit_group;" ::: "memory");
}
__device__ __forceinline__ void cp_wait1() {
    asm volatile("cp.async.wait_group 1;" ::: "memory");
}
__device__ __forceinline__ void cp_wait0() {
    asm volatile("cp.async.wait_group 0;" ::: "memory");
}

// ---------------- K1: rfft, shfl butterfly with smem twiddle LUTs ----------------
__global__ void k_rfft(const float* __restrict__ q,
                       const float* __restrict__ k,
                       const float* __restrict__ v)
{
    __shared__ float2 w32t[16], w64t[32];
    __shared__ float2 zs[8][32];
    int tid = threadIdx.x;
    if (tid < 16) {
        float s, c;
        sincospif(tid * (1.0f/16.0f), &s, &c);   // 2*pi*tid/32
        w32t[tid] = make_float2(c, s);
    } else if (tid < 48) {
        float s, c;
        sincospif((tid - 16) * (1.0f/32.0f), &s, &c); // 2*pi*(tid-16)/64
        w64t[tid - 16] = make_float2(c, s);
    }
    __syncthreads();
    int warp = tid >> 5, lane = tid & 31;
    int r  = blockIdx.x * 8 + warp;
    int l  = r & (LL - 1);
    int bh = r >> 11;
    int b = bh >> 3, h = bh & 7;
    const float* src = (blockIdx.y == 0) ? q : (blockIdx.y == 1) ? k : v;
    const float2* x2 = (const float2*)(src + (((size_t)b*LL + l)*HH + h) * DD);
    float2 z = x2[lane];
    float zr = z.x, zi = z.y;
    #pragma unroll
    for (int s = 0; s < 5; ++s) {
        int hm = 16 >> s;
        float orr = __shfl_xor_sync(0xffffffffu, zr, hm);
        float oii = __shfl_xor_sync(0xffffffffu, zi, hm);
        float2 w = w32t[(lane & (hm - 1)) << s];   // (cos, sin)
        float dx = orr - zr, dy = oii - zi;
        float hr = dx*w.x + dy*w.y;
        float hi = dy*w.x - dx*w.y;
        float lr = zr + orr, li = zi + oii;
        bool top = (lane & hm) != 0;
        zr = top ? hr : lr;
        zi = top ? hi : li;
    }
    int bin = __brev((unsigned)lane) >> 27;
    zs[warp][bin] = make_float2(zr, zi);
    __syncwarp();
    float2 m = zs[warp][(32 - bin) & 31];
    float Zer = 0.5f*(zr + m.x), Zei = 0.5f*(zi - m.y);
    float Zor = 0.5f*(zi + m.y), Zoi = -0.5f*(zr - m.x);
    float2 w = w64t[bin];
    float Xr = Zer + w.x*Zor + w.y*Zoi;
    float Xi = Zei + w.x*Zoi - w.y*Zor;
    float2* out = (blockIdx.y == 0) ? g_qf : (blockIdx.y == 1) ? g_kf : g_vf;
    out[(size_t)r*EE + bin] = make_float2(Xr, Xi);
    if (bin == 0) out[(size_t)r*EE + 32] = make_float2(zr - zi, 0.f);
}

// ---------------- K2: transpose k_fft -> e-major + chunked row-major ----------------
__global__ void k_transpose()
{
    __shared__ float2 tile[32][EE];
    int bh = blockIdx.y;
    int l0 = blockIdx.x * 32;
    for (int t = threadIdx.x; t < 32*EE; t += 256) {
        int r = t / EE, e = t - r*EE;
        tile[r][e] = g_kf[((size_t)bh*LL + l0 + r)*EE + e];
    }
    __syncthreads();
    for (int t = threadIdx.x; t < EE*32; t += 256) {
        int e = t >> 5, r = t & 31;
        g_kfT[((size_t)bh*EE + e)*LL + l0 + r] = tile[r][e];
    }
    for (int t = threadIdx.x; t < 512; t += 256) {
        int half = t >> 8;
        int c    = (t >> 5) & 7;
        int r    = t & 31;
        float2 a = tile[r][c*4 + half*2];
        float2 b = tile[r][c*4 + half*2 + 1];
        g_kfC[(((size_t)(bh*8 + c)) << 12) + (size_t)(l0 + r)*2 + half] =
            make_float4(a.x, a.y, b.x, b.y);
    }
    if (threadIdx.x < 32)
        g_k32[bh*LL + l0 + threadIdx.x] = tile[threadIdx.x][32].x;
}

// ---------------- K2b: time-domain v mean ----------------
__global__ void k_vmt(const float* __restrict__ v)
{
    __shared__ float part[8][64];
    int bh = blockIdx.x, b = bh >> 3, h = bh & 7;
    int tid = threadIdx.x;
    int d = tid & 63, g = tid >> 6;
    const float* base = v + (((size_t)b*LL)*HH + h) * DD + d;
    float acc = 0.f;
    #pragma unroll 8
    for (int i = g; i < LL; i += 8) acc += base[(size_t)i * (HH*DD)];
    part[g][d] = acc;
    __syncthreads();
    if (tid < 64) {
        float s = 0.f;
        #pragma unroll
        for (int g2 = 0; g2 < 8; ++g2) s += part[g2][tid];
        g_vmt[bh*DD + tid] = s * (1.0f/LL);
    }
}

// ---------------- K3: sampled QK -> M (unchanged from R6) ----------------
#define MS_SMEM (131072 + 8192 + 16384)
__global__ void __launch_bounds__(1024, 1) k_msample(const int* __restrict__ isamp)
{
    extern __shared__ char sm[];
    float4* kbuf = (float4*)sm;
    float*  sk32 = (float*)(sm + 131072);
    float4* pt   = (float4*)(sm + 131072 + 8192);

    int tid = threadIdx.x;
    int l0  = blockIdx.x * 256;
    int bh  = blockIdx.y;
    int sg  = tid & 3;
    int lq  = tid >> 2;
    int l   = l0 + lq;

    sk32[tid]        = g_k32[bh*LL + tid];
    sk32[tid + 1024] = g_k32[bh*LL + tid + 1024];

    const int* ip = isamp + l*SK + sg*10;
    int ids[10];
    #pragma unroll
    for (int i = 0; i < 10; ++i) ids[i] = ip[i];

    const float4* kc = g_kfC + (((size_t)(bh*8)) << 12);
    #pragma unroll
    for (int it = 0; it < 4; ++it) {
        int lin = it*1024 + tid;
        int sw  = lin ^ ((lin >> 3) & 7);
        cpa16(&kbuf[sw], &kc[lin]);
    }
    cp_commit();

    float accR[10], accI[10];
    #pragma unroll
    for (int s = 0; s < 10; ++s) { accR[s] = 0.f; accI[s] = 0.f; }
    const float2* qrow = g_qf + (size_t)(bh*LL + l)*EE;

    #pragma unroll 1
    for (int c = 0; c < 8; ++c) {
        int cur = (c & 1) << 12;
        if (c < 7) {
            const float4* src = kc + ((size_t)(c+1) << 12);
            int nb = ((c+1) & 1) << 12;
            #pragma unroll
            for (int it = 0; it < 4; ++it) {
                int lin = it*1024 + tid;
                int sw  = lin ^ ((lin >> 3) & 7);
                cpa16(&kbuf[nb + sw], &src[lin]);
            }
            cp_commit();
            cp_wait1();
        } else {
            cp_wait0();
        }
        __syncthreads();
        float2 q0 = qrow[4*c], q1 = qrow[4*c+1], q2 = qrow[4*c+2], q3 = qrow[4*c+3];
        #pragma unroll
        for (int s = 0; s < 10; ++s) {
            int id = ids[s];
            int p = id << 1, x = (id >> 2) & 7;
            float4 h0 = kbuf[cur + (p ^ x)];
            float4 h1 = kbuf[cur + ((p + 1) ^ x)];
            accR[s] = fmaf(q0.x, h0.x, accR[s]); accR[s] = fmaf(-q0.y, h0.y, accR[s]);
            accI[s] = fmaf(q0.x, h0.y, accI[s]); accI[s] = fmaf( q0.y, h0.x, accI[s]);
            accR[s] = fmaf(q1.x, h0.z, accR[s]); accR[s] = fmaf(-q1.y, h0.w, accR[s]);
            accI[s] = fmaf(q1.x, h0.w, accI[s]); accI[s] = fmaf( q1.y, h0.z, accI[s]);
            accR[s] = fmaf(q2.x, h1.x, accR[s]); accR[s] = fmaf(-q2.y, h1.y, accR[s]);
            accI[s] = fmaf(q2.x, h1.y, accI[s]); accI[s] = fmaf( q2.y, h1.x, accI[s]);
            accR[s] = fmaf(q3.x, h1.z, accR[s]); accR[s] = fmaf(-q3.y, h1.w, accR[s]);
            accI[s] = fmaf(q3.x, h1.w, accI[s]); accI[s] = fmaf( q3.y, h1.z, accI[s]);
        }
        __syncthreads();
    }
    {
        float q32 = qrow[32].x;
        #pragma unroll
        for (int s = 0; s < 10; ++s)
            accR[s] = fmaf(q32, sk32[ids[s]], accR[s]);
    }
    float mr = -3.4e38f, mi = -3.4e38f, sr = 0.f, si = 0.f;
    #pragma unroll
    for (int s = 0; s < 10; ++s) {
        mr = fmaxf(mr, accR[s]); mi = fmaxf(mi, accI[s]);
        sr += accR[s];           si += accI[s];
    }
    pt[sg*256 + lq] = make_float4(mr, mi, sr, si);
    __syncthreads();
    if (tid < 256) {
        float4 a = pt[tid], b = pt[256 + tid], c2 = pt[512 + tid], d = pt[768 + tid];
        float MR = fmaxf(fmaxf(a.x, b.x), fmaxf(c2.x, d.x));
        float MI = fmaxf(fmaxf(a.y, b.y), fmaxf(c2.y, d.y));
        float SR = a.z + b.z + c2.z + d.z;
        float SI = a.w + b.w + c2.w + d.w;
        g_M[(size_t)bh*LL + l0 + tid] = MR + MI - (SR + SI) * (1.0f/LL);
    }
}

// ---------------- K4: top-40 per bh ----------------
__global__ void k_topk()
{
    __shared__ float mv[LL];
    __shared__ float wv[8];
    __shared__ int   wi[8];
    int bh = blockIdx.x, tid = threadIdx.x, lane = tid & 31, warp = tid >> 5;
    for (int i = tid; i < LL; i += 256) {
        mv[i] = g_M[bh*LL + i];
        g_slot[bh*LL + i] = -1;
    }
    __syncthreads();
    for (int u = 0; u < UU; ++u) {
        float best = -3.4e38f; int bi = 1 << 30;
        for (int i = tid; i < LL; i += 256) {
            float x = mv[i];
            if (x > best) { best = x; bi = i; }
        }
        #pragma unroll
        for (int o = 16; o; o >>= 1) {
            float ov = __shfl_xor_sync(0xffffffffu, best, o);
            int   oi = __shfl_xor_sync(0xffffffffu, bi, o);
            if (ov > best || (ov == best && oi < bi)) { best = ov; bi = oi; }
        }
        if (lane == 0) { wv[warp] = best; wi[warp] = bi; }
        __syncthreads();
        if (warp == 0) {
            float b2 = (lane < 8) ? wv[lane] : -3.4e38f;
            int   i2 = (lane < 8) ? wi[lane] : (1 << 30);
            #pragma unroll
            for (int o = 4; o; o >>= 1) {
                float ov = __shfl_xor_sync(0xffffffffu, b2, o);
                int   oi = __shfl_xor_sync(0xffffffffu, i2, o);
                if (ov > b2 || (ov == b2 && oi < i2)) { b2 = ov; i2 = oi; }
            }
            if (lane == 0) {
                g_top[bh*UU + u] = i2;
                g_slot[bh*LL + i2] = u;
                mv[i2] = -3.4e38f;
            }
        }
        __syncthreads();
    }
}

// ---------------- K5: full scores, 20-u register blocked ----------------
__global__ void __launch_bounds__(512) k_scores()
{
    __shared__ float2 shq[20][EE];
    int bh = blockIdx.z;
    int ug = blockIdx.y;
    int jt = blockIdx.x;
    int tid = threadIdx.x;
    for (int t = tid; t < 20*EE; t += 512) {
        int ul = t / EE, e = t - ul*EE;
        int qi = g_top[bh*UU + ug*20 + ul];
        shq[ul][e] = g_qf[((size_t)bh*LL + qi)*EE + e];
    }
    __syncthreads();
    int j = jt*512 + tid;
    float accR[20], accI[20];
    #pragma unroll
    for (int u = 0; u < 20; ++u) { accR[u] = 0.f; accI[u] = 0.f; }
    const float2* kT = g_kfT + (size_t)bh*EE*LL + j;
    for (int e = 0; e < EE; ++e) {
        float2 kv = kT[(size_t)e*LL];
        #pragma unroll
        for (int u = 0; u < 20; ++u) {
            float2 qv = shq[u][e];
            accR[u] = fmaf(qv.x, kv.x, accR[u]); accR[u] = fmaf(-qv.y, kv.y, accR[u]);
            accI[u] = fmaf(qv.x, kv.y, accI[u]); accI[u] = fmaf( qv.y, kv.x, accI[u]);
        }
    }
    const float sc = 0.125f;
    #pragma unroll
    for (int u = 0; u < 20; ++u)
        g_big[((size_t)bh*UU + ug*20 + u)*LL + j] = make_float2(accR[u]*sc, accI[u]*sc);
}

// ---------------- K6: fused softmax + upd (8 u per block) ----------------
#define SMU_SMEM (131072 + 33792 + 256)
__global__ void __launch_bounds__(512, 1) k_smupd()
{
    extern __shared__ char smc[];
    float2* p    = (float2*)smc;                       // [8][2048]
    float2* accs = (float2*)(smc + 131072);            // [16][8][33]
    float2* mxs  = (float2*)(smc + 131072 + 33792);    // [16] then reused as sums
    int bh = blockIdx.y, ug = blockIdx.x;
    int tid = threadIdx.x, warp = tid >> 5, lane = tid & 31;

    const float2* gb = g_big + ((size_t)bh*UU + ug*8)*LL;
    for (int i = tid; i < 8*LL; i += 512)
        p[i] = gb[i];                                  // u-major contiguous == layout
    __syncthreads();

    // softmax: warp w -> row u = w>>1, half = w&1 (1024 elems each)
    int su = warp >> 1, half = warp & 1;
    float2* row = p + (su << 11) + (half << 10);
    float mr = -3.4e38f, mi = -3.4e38f;
    #pragma unroll 8
    for (int k2 = 0; k2 < 32; ++k2) {
        float2 vv = row[lane + k2*32];
        mr = fmaxf(mr, vv.x); mi = fmaxf(mi, vv.y);
    }
    #pragma unroll
    for (int o = 16; o; o >>= 1) {
        mr = fmaxf(mr, __shfl_xor_sync(0xffffffffu, mr, o));
        mi = fmaxf(mi, __shfl_xor_sync(0xffffffffu, mi, o));
    }
    if (lane == 0) mxs[warp] = make_float2(mr, mi);
    __syncthreads();
    {
        float2 a = mxs[su*2], b = mxs[su*2+1];
        mr = fmaxf(a.x, b.x); mi = fmaxf(a.y, b.y);
    }
    __syncthreads();          // all reads of mxs done before reuse
    float sr = 0.f, si = 0.f;
    #pragma unroll 8
    for (int k2 = 0; k2 < 32; ++k2) {
        float2 vv = row[lane + k2*32];
        float er = __expf(vv.x - mr);
        float ei = __expf(vv.y - mi);
        row[lane + k2*32] = make_float2(er, ei);
        sr += er; si += ei;
    }
    #pragma unroll
    for (int o = 16; o; o >>= 1) {
        sr += __shfl_xor_sync(0xffffffffu, sr, o);
        si += __shfl_xor_sync(0xffffffffu, si, o);
    }
    if (lane == 0) mxs[warp] = make_float2(sr, si);
    __syncthreads();
    {
        float2 a = mxs[su*2], b = mxs[su*2+1];
        float inr = 1.0f / (a.x + b.x);
        float ini = 1.0f / (a.y + b.y);
        #pragma unroll 8
        for (int k2 = 0; k2 < 32; ++k2) {
            float2 vv = row[lane + k2*32];
            row[lane + k2*32] = make_float2(vv.x * inr, vv.y * ini);
        }
    }
    __syncthreads();

    // upd: warp-strided over l, lane = e
    float aR[8], aI[8], aR2[8], aI2[8];
    #pragma unroll
    for (int u = 0; u < 8; ++u) { aR[u]=aI[u]=aR2[u]=aI2[u]=0.f; }
    const float2* vb = g_vf + (size_t)bh*LL*EE;
    for (int l = warp; l < LL; l += 16) {
        float2 v2 = vb[(size_t)l*EE + lane];
        float2 v32 = make_float2(0.f, 0.f);
        if (lane == 0) v32 = vb[(size_t)l*EE + 32];
        #pragma unroll
        for (int u = 0; u < 8; ++u) {
            float2 pp = p[(u << 11) + l];
            aR[u]  = fmaf(pp.x, v2.x,  aR[u]);
            aI[u]  = fmaf(pp.y, v2.y,  aI[u]);
            aR2[u] = fmaf(pp.x, v32.x, aR2[u]);
            aI2[u] = fmaf(pp.y, v32.y, aI2[u]);
        }
    }
    #pragma unroll
    for (int u = 0; u < 8; ++u) {
        accs[(warp*8 + u)*EE + lane] = make_float2(aR[u], aI[u]);
        if (lane == 0) accs[(warp*8 + u)*EE + 32] = make_float2(aR2[u], aI2[u]);
    }
    __syncthreads();
    for (int t = tid; t < 8*EE; t += 512) {
        int u = t / EE, e = t - u*EE;
        float ssr = 0.f, ssi = 0.f;
        #pragma unroll
        for (int w = 0; w < 16; ++w) {
            float2 a = accs[(w*8 + u)*EE + e];
            ssr += a.x; ssi += a.y;
        }
        g_upd[((size_t)bh*UU + ug*8 + u)*EE + e] = make_float2(ssr, ssi);
    }
}

// ---------------- K7: scatter + irfft of selected rows ----------------
__global__ void k_out(float* __restrict__ out)
{
    __shared__ float tc[64], ts[64];
    __shared__ float2 ub[8][EE];
    int tid = threadIdx.x;
    if (tid < 64) {
        float s, c;
        sincospif(tid * (1.0f/32.0f), &s, &c);
        tc[tid] = c; ts[tid] = s;
    }
    __syncthreads();
    int warp = tid >> 5, lane = tid & 31;
    int r = blockIdx.x * 8 + warp;
    int bh = r >> 11;
    int slot = g_slot[r];
    float* op = out + (size_t)r * DD;
    if (slot < 0) {
        op[lane]      = g_vmt[bh*DD + lane];
        op[lane + 32] = g_vmt[bh*DD + lane + 32];
    } else {
        const float2* X = g_upd + ((size_t)bh*UU + slot)*EE;
        ub[warp][lane] = X[lane];
        if (lane == 0) ub[warp][32] = X[32];
        __syncwarp();
        float a0 = ub[warp][0].x;
        float a32 = ub[warp][32].x;
        float sgn = (lane & 1) ? -a32 : a32;
        float acc1 = a0 + sgn, acc2 = a0 + sgn;
        #pragma unroll
        for (int e = 1; e < 32; ++e) {
            float2 Xe = ub[warp][e];
            int j1 = (e * lane) & 63;
            int j2 = (e * (lane + 32)) & 63;
            acc1 += 2.f * (Xe.x*tc[j1] - Xe.y*ts[j1]);
            acc2 += 2.f * (Xe.x*tc[j2] - Xe.y*ts[j2]);
        }
        op[lane]      = acc1 * (1.0f/64.0f);
        op[lane + 32] = acc2 * (1.0f/64.0f);
    }
}

// ---------------- launch ----------------
extern "C" void kernel_launch(void* const* d_in, const int* in_sizes, int n_in,
                              void* d_out, int out_size)
{
    (void)in_sizes; (void)n_in; (void)out_size;
    const float* q = (const float*)d_in[0];
    const float* k = (const float*)d_in[1];
    const float* v = (const float*)d_in[2];
    const int* isamp = (const int*)d_in[4];
    float* out = (float*)d_out;

    cudaFuncSetAttribute(k_msample, cudaFuncAttributeMaxDynamicSharedMemorySize, MS_SMEM);
    cudaFuncSetAttribute(k_smupd,   cudaFuncAttributeMaxDynamicSharedMemorySize, SMU_SMEM);

    k_rfft     <<<dim3(ROWS/8, 3), 256>>>(q, k, v);
    k_transpose<<<dim3(LL/32, BHN), 256>>>();
    k_vmt      <<<BHN, 512>>>(v);
    k_msample  <<<dim3(LL/256, BHN), 1024, MS_SMEM>>>(isamp);
    k_topk     <<<BHN, 256>>>();
    k_scores   <<<dim3(4, 2, BHN), 512>>>();
    k_smupd    <<<dim3(5, BHN), 512, SMU_SMEM>>>();
    k_out      <<<ROWS/8, 256>>>(out);
}